// round 5
// baseline (speedup 1.0000x reference)
#include <cuda_runtime.h>
#include <cuda_bf16.h>
#include <cstdint>
#include <cstddef>

#define S_LEN 2048
#define E_DIM 4096
#define H_NUM 16
#define D_DIM 256
#define RD_DIM 64
#define EW (E_DIM / 2)   // u32 words per E row
#define SW (S_LEN / 2)   // u32 words per S row

// ---------------- scratch ----------------
__device__ __align__(16) float g_Q[(size_t)S_LEN * E_DIM];
__device__ __align__(16) float g_K[(size_t)S_LEN * E_DIM];
__device__ __align__(16) float g_V[(size_t)S_LEN * E_DIM];
__device__ __align__(16) float g_ATT[(size_t)S_LEN * E_DIM];
__device__ __align__(16) float g_P[(size_t)H_NUM * S_LEN * S_LEN];

__device__ __align__(16) uint32_t g_HH[(size_t)S_LEN * EW];
__device__ __align__(16) uint32_t g_HL[(size_t)S_LEN * EW];
__device__ __align__(16) uint32_t g_QH[(size_t)S_LEN * EW];
__device__ __align__(16) uint32_t g_QL[(size_t)S_LEN * EW];
__device__ __align__(16) uint32_t g_KH[(size_t)S_LEN * EW];
__device__ __align__(16) uint32_t g_KL[(size_t)S_LEN * EW];
__device__ __align__(16) uint32_t g_AH[(size_t)S_LEN * EW];
__device__ __align__(16) uint32_t g_AL[(size_t)S_LEN * EW];
__device__ __align__(16) uint32_t g_WH[(size_t)E_DIM * EW];
__device__ __align__(16) uint32_t g_WL[(size_t)E_DIM * EW];
__device__ __align__(16) uint32_t g_VTH[(size_t)H_NUM * D_DIM * SW];
__device__ __align__(16) uint32_t g_VTL[(size_t)H_NUM * D_DIM * SW];
__device__ __align__(16) uint32_t g_PH[(size_t)H_NUM * S_LEN * SW];
__device__ __align__(16) uint32_t g_PL[(size_t)H_NUM * S_LEN * SW];

// ---------------- helpers ----------------
__device__ __forceinline__ uint32_t pack_split(float x, float y, uint32_t& lo) {
    __nv_bfloat162 h = __floats2bfloat162_rn(x, y);
    float rx = x - __bfloat162float(h.x);
    float ry = y - __bfloat162float(h.y);
    __nv_bfloat162 l = __floats2bfloat162_rn(rx, ry);
    lo = *reinterpret_cast<uint32_t*>(&l);
    return *reinterpret_cast<uint32_t*>(&h);
}

__device__ __forceinline__ uint32_t smem_u32(const void* p) {
    uint32_t a;
    asm("{ .reg .u64 t; cvta.to.shared.u64 t, %1; cvt.u32.u64 %0, t; }" : "=r"(a) : "l"(p));
    return a;
}

__device__ __forceinline__ void mma16(float c[4], const uint32_t a[4],
                                      uint32_t b0, uint32_t b1) {
    asm volatile(
        "mma.sync.aligned.m16n8k16.row.col.f32.bf16.bf16.f32 "
        "{%0,%1,%2,%3},{%4,%5,%6,%7},{%8,%9},{%0,%1,%2,%3};\n"
        : "+f"(c[0]), "+f"(c[1]), "+f"(c[2]), "+f"(c[3])
        : "r"(a[0]), "r"(a[1]), "r"(a[2]), "r"(a[3]), "r"(b0), "r"(b1));
}

__device__ __forceinline__ void cpa16(uint32_t dst, const uint32_t* src) {
    asm volatile("cp.async.cg.shared.global [%0], [%1], 16;" :: "r"(dst), "l"(src));
}
__device__ __forceinline__ void cpa_commit() {
    asm volatile("cp.async.commit_group;" ::: "memory");
}
template<int N>
__device__ __forceinline__ void cpa_wait() {
    asm volatile("cp.async.wait_group %0;" :: "n"(N) : "memory");
}

// ---------------- GEMM: 128 x 256 C tiles, legacy mma.sync, 3xBF16 ----------------
// A: M x K K-major hi/lo planes of bf16x2 words (k-pairs). B: N x K same format.
// Per 32-k stage, smem layout (u32 words, row stride 20 = 16 data + 4 pad):
//   [AH 128*20 | AL 128*20 | BH 256*20 | BL 256*20] = 15360 words
#define BM 128
#define BN 256
#define ASTR 20
#define A_PL (128 * ASTR)        // 2560
#define B_PL (256 * ASTR)        // 5120
#define STG_W (2 * A_PL + 2 * B_PL)   // 15360 words
#define SMEM_GEMM (2 * STG_W * 4)     // 122880 bytes

template<bool SKIP_UPPER, bool KLIMIT>
__global__ void __launch_bounds__(256, 1)
gemm_ls(const uint32_t* __restrict__ aH, const uint32_t* __restrict__ aL,
        int lda, size_t sA,
        const uint32_t* __restrict__ bH, const uint32_t* __restrict__ bL,
        int ldb, size_t sB,
        float* __restrict__ C, int ldc, size_t sC,
        int K, float alpha)
{
    if (SKIP_UPPER && 2 * blockIdx.x > blockIdx.y) return;
    aH += blockIdx.z * sA;  aL += blockIdx.z * sA;
    bH += blockIdx.z * sB;  bL += blockIdx.z * sB;
    C  += blockIdx.z * sC;

    const int bm = blockIdx.y * BM;
    const int bn = blockIdx.x * BN;
    const int Keff  = KLIMIT ? min(K, (int)(blockIdx.y + 1) * BM) : K;
    const int niter = Keff >> 5;          // 32 k-elems (16 words) per iter

    extern __shared__ uint32_t sm[];
    const uint32_t sb = smem_u32(sm);

    const int tid  = threadIdx.x;
    const int lane = tid & 31;
    const int warp = tid >> 5;
    const int wm   = (warp >> 2) * 64;    // 2 warps in m
    const int wn   = (warp & 3) * 64;     // 4 warps in n
    const int lr   = lane >> 2;
    const int lc   = lane & 3;

    const uint32_t* aP[2] = { aH + (size_t)bm * lda, aL + (size_t)bm * lda };
    const uint32_t* bP[2] = { bH + (size_t)bn * ldb, bL + (size_t)bn * ldb };

    // ---- async producer: stage 'it' ----
    auto issue = [&](int it) {
        const int k0w = it << 4;
        const uint32_t stg = sb + (it & 1) * (STG_W * 4);
#pragma unroll
        for (int i = 0; i < 4; i++) {                 // A: 1024 uint4
            int lin = i * 256 + tid;
            int pl = lin >> 9, rem = lin & 511;
            int row = rem >> 2, q = rem & 3;
            cpa16(stg + (pl * A_PL + row * ASTR + q * 4) * 4,
                  aP[pl] + (size_t)row * lda + k0w + q * 4);
        }
#pragma unroll
        for (int i = 0; i < 8; i++) {                 // B: 2048 uint4
            int lin = i * 256 + tid;
            int pl = lin >> 10, rem = lin & 1023;
            int row = rem >> 2, q = rem & 3;
            cpa16(stg + (2 * A_PL + pl * B_PL + row * ASTR + q * 4) * 4,
                  bP[pl] + (size_t)row * ldb + k0w + q * 4);
        }
        cpa_commit();
    };

    float acc[4][8][4];
#pragma unroll
    for (int i = 0; i < 4; i++)
#pragma unroll
        for (int j = 0; j < 8; j++)
#pragma unroll
            for (int r = 0; r < 4; r++) acc[i][j][r] = 0.f;

    issue(0);
    for (int it = 0; it < niter; ++it) {
        if (it + 1 < niter) { issue(it + 1); cpa_wait<1>(); }
        else                { cpa_wait<0>(); }
        __syncthreads();

        const uint32_t* AHs = sm + (it & 1) * STG_W;
        const uint32_t* ALs = AHs + A_PL;
        const uint32_t* BHs = ALs + A_PL;
        const uint32_t* BLs = BHs + B_PL;

#pragma unroll
        for (int kk = 0; kk < 16; kk += 8) {          // two 16-k mma steps
            uint32_t ah[4][4], al[4][4];
#pragma unroll
            for (int mt = 0; mt < 4; mt++) {
                int r0 = (wm + mt * 16 + lr) * ASTR + kk + lc;
                ah[mt][0] = AHs[r0];
                ah[mt][1] = AHs[r0 + 8 * ASTR];
                ah[mt][2] = AHs[r0 + 4];
                ah[mt][3] = AHs[r0 + 8 * ASTR + 4];
                al[mt][0] = ALs[r0];
                al[mt][1] = ALs[r0 + 8 * ASTR];
                al[mt][2] = ALs[r0 + 4];
                al[mt][3] = ALs[r0 + 8 * ASTR + 4];
            }
#pragma unroll
            for (int nt = 0; nt < 8; nt++) {
                int nb = (wn + nt * 8 + lr) * ASTR + kk + lc;
                uint32_t bh0 = BHs[nb], bh1 = BHs[nb + 4];
                uint32_t bl0 = BLs[nb], bl1 = BLs[nb + 4];
#pragma unroll
                for (int mt = 0; mt < 4; mt++) {
                    mma16(acc[mt][nt], ah[mt], bh0, bh1);   // hi*hi
                    mma16(acc[mt][nt], ah[mt], bl0, bl1);   // hi*lo
                    mma16(acc[mt][nt], al[mt], bh0, bh1);   // lo*hi
                }
            }
        }
        __syncthreads();
    }

    // ---- epilogue ----
#pragma unroll
    for (int mt = 0; mt < 4; mt++)
#pragma unroll
        for (int nt = 0; nt < 8; nt++) {
            int r0 = bm + wm + mt * 16 + lr;
            int c0 = bn + wn + nt * 8 + lc * 2;
            float2 v0 = make_float2(acc[mt][nt][0] * alpha, acc[mt][nt][1] * alpha);
            float2 v1 = make_float2(acc[mt][nt][2] * alpha, acc[mt][nt][3] * alpha);
            *reinterpret_cast<float2*>(C + (size_t)r0 * ldc + c0)       = v0;
            *reinterpret_cast<float2*>(C + (size_t)(r0 + 8) * ldc + c0) = v1;
        }
}

// ---------------- split f32 row-major -> bf16 hi/lo k-pair words ----------------
__global__ void split2(const float* __restrict__ in, uint32_t* __restrict__ oh,
                       uint32_t* __restrict__ ol)
{
    size_t i = (size_t)blockIdx.x * 256 + threadIdx.x;
    float4 v = reinterpret_cast<const float4*>(in)[i];
    uint32_t l0, l1;
    uint32_t h0 = pack_split(v.x, v.y, l0);
    uint32_t h1 = pack_split(v.z, v.w, l1);
    reinterpret_cast<uint2*>(oh)[i] = make_uint2(h0, h1);
    reinterpret_cast<uint2*>(ol)[i] = make_uint2(l0, l1);
}

// ---------------- transpose+split: f32 [K][N] -> hi/lo [N][K/2 words] ----------------
__global__ void tsplit(const float* __restrict__ in, int ldin, size_t sIn,
                       uint32_t* __restrict__ oh, uint32_t* __restrict__ ol,
                       int ldo, size_t sOut)
{
    in += blockIdx.z * sIn;
    oh += blockIdx.z * sOut;
    ol += blockIdx.z * sOut;
    const int k0 = blockIdx.x * 32, n0 = blockIdx.y * 32;
    __shared__ float ts[32][33];
    const int tx = threadIdx.x, ty = threadIdx.y;   // 16 x 16
#pragma unroll
    for (int j = 0; j < 2; j++) {
        float2 v = *reinterpret_cast<const float2*>(
            in + (size_t)(k0 + ty + j * 16) * ldin + n0 + tx * 2);
        ts[ty + j * 16][tx * 2]     = v.x;
        ts[ty + j * 16][tx * 2 + 1] = v.y;
    }
    __syncthreads();
#pragma unroll
    for (int j = 0; j < 2; j++) {
        int n = ty + j * 16;
        uint32_t lo;
        uint32_t hi = pack_split(ts[tx * 2][n], ts[tx * 2 + 1][n], lo);
        size_t o = (size_t)(n0 + n) * ldo + (k0 >> 1) + tx;
        oh[o] = hi;
        ol[o] = lo;
    }
}

// ---------------- RoPE ----------------
__global__ void rope_kernel(float* __restrict__ Q, float* __restrict__ Km,
                            const int* __restrict__ pos)
{
    const int s = blockIdx.x;
    const float p = (float)pos[s];
    for (int idx = threadIdx.x; idx < H_NUM * (RD_DIM / 2); idx += blockDim.x) {
        int h = idx >> 5;
        int j = idx & 31;
        float inv = exp2f(-0.41524101186092033f * (float)j);
        float sn, cs;
        __sincosf(p * inv, &sn, &cs);
        size_t base = (size_t)s * E_DIM + (size_t)h * D_DIM + 2 * j;
        float q0 = Q[base], q1 = Q[base + 1];
        Q[base]     = q0 * cs - q1 * sn;
        Q[base + 1] = q1 * cs + q0 * sn;
        float k0 = Km[base], k1 = Km[base + 1];
        Km[base]     = k0 * cs - k1 * sn;
        Km[base + 1] = k1 * cs + k0 * sn;
    }
}

// ---------------- causal softmax f32 -> bf16 hi/lo P (zero-filled to 128 edge) ----------------
__global__ void softmax_causal(const float* __restrict__ P,
                               uint32_t* __restrict__ PH, uint32_t* __restrict__ PL)
{
    const int m = blockIdx.x, h = blockIdx.y, tid = threadIdx.x;
    const float* row = P + ((size_t)h * S_LEN + m) * S_LEN;
    uint32_t* oh = PH + ((size_t)h * S_LEN + m) * SW;
    uint32_t* ol = PL + ((size_t)h * S_LEN + m) * SW;
    const int nv = m + 1;
    const int nfw = ((((m >> 7) + 1) << 7) >> 1);   // words to fill
    __shared__ float sh[8];

    float mx = -3.4e38f;
    for (int n = tid; n < nv; n += 256) mx = fmaxf(mx, row[n]);
#pragma unroll
    for (int o = 16; o; o >>= 1) mx = fmaxf(mx, __shfl_xor_sync(0xffffffffu, mx, o));
    if ((tid & 31) == 0) sh[tid >> 5] = mx;
    __syncthreads();
    float bmax = sh[0];
#pragma unroll
    for (int w = 1; w < 8; w++) bmax = fmaxf(bmax, sh[w]);
    __syncthreads();

    float s = 0.f;
    for (int n = tid; n < nv; n += 256) s += __expf(row[n] - bmax);
#pragma unroll
    for (int o = 16; o; o >>= 1) s += __shfl_xor_sync(0xffffffffu, s, o);
    if ((tid & 31) == 0) sh[tid >> 5] = s;
    __syncthreads();
    float tot = 0.f;
#pragma unroll
    for (int w = 0; w < 8; w++) tot += sh[w];
    float inv = 1.f / tot;

    for (int w = tid; w < nfw; w += 256) {
        int n0 = 2 * w;
        float e0 = (n0     < nv) ? __expf(row[n0]     - bmax) * inv : 0.f;
        float e1 = (n0 + 1 < nv) ? __expf(row[n0 + 1] - bmax) * inv : 0.f;
        uint32_t lo;
        uint32_t hi = pack_split(e0, e1, lo);
        oh[w] = hi;
        ol[w] = lo;
    }
}

// ---------------- launch ----------------
extern "C" void kernel_launch(void* const* d_in, const int* in_sizes, int n_in,
                              void* d_out, int out_size)
{
    const float* hidden = (const float*)d_in[0];
    const float* wq     = (const float*)d_in[1];
    const float* wk     = (const float*)d_in[2];
    const float* wv     = (const float*)d_in[3];
    const float* wo     = (const float*)d_in[4];
    const int*   pos    = (const int*)d_in[5];
    float* out = (float*)d_out;

    float *Q, *K, *V, *ATT, *P;
    uint32_t *HH, *HL, *QH, *QL, *KH, *KL, *AH, *AL, *WH, *WL, *VTH, *VTL, *PH, *PL;
    cudaGetSymbolAddress((void**)&Q, g_Q);     cudaGetSymbolAddress((void**)&K, g_K);
    cudaGetSymbolAddress((void**)&V, g_V);     cudaGetSymbolAddress((void**)&ATT, g_ATT);
    cudaGetSymbolAddress((void**)&P, g_P);
    cudaGetSymbolAddress((void**)&HH, g_HH);   cudaGetSymbolAddress((void**)&HL, g_HL);
    cudaGetSymbolAddress((void**)&QH, g_QH);   cudaGetSymbolAddress((void**)&QL, g_QL);
    cudaGetSymbolAddress((void**)&KH, g_KH);   cudaGetSymbolAddress((void**)&KL, g_KL);
    cudaGetSymbolAddress((void**)&AH, g_AH);   cudaGetSymbolAddress((void**)&AL, g_AL);
    cudaGetSymbolAddress((void**)&WH, g_WH);   cudaGetSymbolAddress((void**)&WL, g_WL);
    cudaGetSymbolAddress((void**)&VTH, g_VTH); cudaGetSymbolAddress((void**)&VTL, g_VTL);
    cudaGetSymbolAddress((void**)&PH, g_PH);   cudaGetSymbolAddress((void**)&PL, g_PL);

    cudaFuncSetAttribute(gemm_ls<false, false>, cudaFuncAttributeMaxDynamicSharedMemorySize, SMEM_GEMM);
    cudaFuncSetAttribute(gemm_ls<true,  false>, cudaFuncAttributeMaxDynamicSharedMemorySize, SMEM_GEMM);
    cudaFuncSetAttribute(gemm_ls<false, true >, cudaFuncAttributeMaxDynamicSharedMemorySize, SMEM_GEMM);

    const dim3 b256(256);
    const dim3 tblk(16, 16);
    const dim3 gw(E_DIM / 32, E_DIM / 32, 1);
    const dim3 gproj(E_DIM / BN, S_LEN / BM, 1);
    const int nsplit = (S_LEN * E_DIM / 4) / 256;

    // hidden split once
    split2<<<nsplit, b256>>>(hidden, HH, HL);

    // projections (weights transposed+split into W buffer, serially reused)
    tsplit<<<gw, tblk>>>(wq, E_DIM, 0, WH, WL, EW, 0);
    gemm_ls<false, false><<<gproj, b256, SMEM_GEMM>>>(HH, HL, EW, 0, WH, WL, EW, 0, Q, E_DIM, 0, E_DIM, 1.f);
    tsplit<<<gw, tblk>>>(wk, E_DIM, 0, WH, WL, EW, 0);
    gemm_ls<false, false><<<gproj, b256, SMEM_GEMM>>>(HH, HL, EW, 0, WH, WL, EW, 0, K, E_DIM, 0, E_DIM, 1.f);
    tsplit<<<gw, tblk>>>(wv, E_DIM, 0, WH, WL, EW, 0);
    gemm_ls<false, false><<<gproj, b256, SMEM_GEMM>>>(HH, HL, EW, 0, WH, WL, EW, 0, V, E_DIM, 0, E_DIM, 1.f);

    // RoPE then split Q/K; transpose+split V per head
    rope_kernel<<<S_LEN, b256>>>(Q, K, pos);
    split2<<<nsplit, b256>>>(Q, QH, QL);
    split2<<<nsplit, b256>>>(K, KH, KL);
    tsplit<<<dim3(S_LEN / 32, D_DIM / 32, H_NUM), tblk>>>(
        V, E_DIM, (size_t)D_DIM, VTH, VTL, SW, (size_t)D_DIM * SW);

    // scores[h] = (Q_h @ K_h^T) / 16 (upper-tri CTAs skipped)
    gemm_ls<true, false><<<dim3(S_LEN / BN, S_LEN / BM, H_NUM), b256, SMEM_GEMM>>>(
        QH, QL, EW, (size_t)(D_DIM / 2),
        KH, KL, EW, (size_t)(D_DIM / 2),
        P, S_LEN, (size_t)S_LEN * S_LEN, D_DIM, 0.0625f);

    // softmax -> bf16 hi/lo P
    softmax_causal<<<dim3(S_LEN, H_NUM), b256>>>(P, PH, PL);

    // attn[h] = P_h @ V_h (K causally clamped)
    gemm_ls<false, true><<<dim3(D_DIM / BN, S_LEN / BM, H_NUM), b256, SMEM_GEMM>>>(
        PH, PL, SW, (size_t)S_LEN * SW,
        VTH, VTL, SW, (size_t)D_DIM * SW,
        ATT, E_DIM, (size_t)D_DIM, S_LEN, 1.f);

    // out = attn @ wo
    split2<<<nsplit, b256>>>(ATT, AH, AL);
    tsplit<<<gw, tblk>>>(wo, E_DIM, 0, WH, WL, EW, 0);
    gemm_ls<false, false><<<gproj, b256, SMEM_GEMM>>>(AH, AL, EW, 0, WH, WL, EW, 0, out, E_DIM, 0, E_DIM, 1.f);
}